// round 2
// baseline (speedup 1.0000x reference)
#include <cuda_runtime.h>
#include <cstdint>
#include <cstddef>

// ---------------------------------------------------------------------------
// RGCN 2-layer, mean agg, ReLU, L2 norm. N=100000, E=1600000, R=2, 128->128->64.
// Round 2: CSR-gather aggregation (no atomics on features, built once) +
//          f32x2 packed-FMA SIMT GEMM.
// ---------------------------------------------------------------------------

#define NN   100000
#define NE   1600000
#define NREL 2
#define CIN  128
#define CHID 128
#define COUT 64

#define SCAN_N (NREL * NN)          // 200000 buckets
#define SBS    512
#define SNB    ((SCAN_N + SBS - 1) / SBS)   // 391

// Scratch (static device globals; no allocation allowed).
__device__ __align__(128) float g_agg[(size_t)NREL * NN * CIN];   // 102.4 MB
__device__ __align__(128) float g_h[(size_t)NN * CHID];           // 51.2 MB
__device__ int g_icnt[SCAN_N];
__device__ int g_off[SCAN_N];
__device__ int g_cur[SCAN_N];
__device__ int g_bsum[SNB];
__device__ int g_srcs[NE];
__device__ int g_is64;

// ---------------------------------------------------------------------------
// Edge dtype detection (jax x64-disabled silently downcasts int64 -> int32).
// ---------------------------------------------------------------------------
__global__ void detect_kernel(const void* et) {
    const long long* p = (const long long*)et;
    int ok = 1;
    for (int i = 0; i < 512; i++) {
        long long v = p[i];
        if (v < 0 || v >= NREL) { ok = 0; break; }
    }
    g_is64 = ok;
}

__device__ __forceinline__ long long ld_idx(const void* p, long long i, int is64) {
    if (is64) return ((const long long*)p)[i];
    return (long long)((const int*)p)[i];
}

// ---------------------------------------------------------------------------
// CSR build: count -> scan (2-level) -> place.
// ---------------------------------------------------------------------------
__global__ void zero_icnt_kernel() {
    int i = blockIdx.x * blockDim.x + threadIdx.x;
    if (i < SCAN_N) g_icnt[i] = 0;
}

__global__ void count_kernel(const void* ei, const void* et) {
    int e = blockIdx.x * blockDim.x + threadIdx.x;
    if (e >= NE) return;
    int is64 = g_is64;
    int dst = (int)ld_idx(ei, (long long)NE + e, is64);
    int r   = (int)ld_idx(et, e, is64);
    atomicAdd(&g_icnt[r * NN + dst], 1);
}

__global__ void scan1_kernel() {
    __shared__ int s[SBS];
    int tid = threadIdx.x;
    int i = blockIdx.x * SBS + tid;
    int v = (i < SCAN_N) ? g_icnt[i] : 0;
    s[tid] = v;
    __syncthreads();
#pragma unroll
    for (int o = 1; o < SBS; o <<= 1) {
        int t = 0;
        if (tid >= o) t = s[tid - o];
        __syncthreads();
        if (tid >= o) s[tid] += t;
        __syncthreads();
    }
    if (i < SCAN_N) g_off[i] = s[tid] - v;          // exclusive within block
    if (tid == SBS - 1) g_bsum[blockIdx.x] = s[SBS - 1];
}

__global__ void scan2_kernel() {
    __shared__ int s[SBS];
    int tid = threadIdx.x;
    int v = (tid < SNB) ? g_bsum[tid] : 0;
    s[tid] = v;
    __syncthreads();
#pragma unroll
    for (int o = 1; o < SBS; o <<= 1) {
        int t = 0;
        if (tid >= o) t = s[tid - o];
        __syncthreads();
        if (tid >= o) s[tid] += t;
        __syncthreads();
    }
    if (tid < SNB) g_bsum[tid] = s[tid] - v;        // exclusive block offsets
}

__global__ void scan3_kernel() {
    int i = blockIdx.x * blockDim.x + threadIdx.x;
    if (i >= SCAN_N) return;
    int o = g_off[i] + g_bsum[i / SBS];
    g_off[i] = o;
    g_cur[i] = o;
}

__global__ void place_kernel(const void* ei, const void* et) {
    int e = blockIdx.x * blockDim.x + threadIdx.x;
    if (e >= NE) return;
    int is64 = g_is64;
    int src = (int)ld_idx(ei, e, is64);
    int dst = (int)ld_idx(ei, (long long)NE + e, is64);
    int r   = (int)ld_idx(et, e, is64);
    int p = atomicAdd(&g_cur[r * NN + dst], 1);
    g_srcs[p] = src;
}

// ---------------------------------------------------------------------------
// Gather-aggregate: one warp per (rel,node) bucket. Lane l owns channels
// [4l,4l+4). Pure loads + one plain store; mean folded in. Overwrites all
// rows, so no zero pass is needed.
// ---------------------------------------------------------------------------
__global__ void gather_kernel(const float* __restrict__ x, int use_h) {
    int gt = blockIdx.x * blockDim.x + threadIdx.x;
    int w = gt >> 5;
    int lane = gt & 31;
    if (w >= SCAN_N) return;
    const float* __restrict__ base = use_h ? g_h : x;
    int off = g_off[w];
    int cnt = g_icnt[w];
    float4 acc = make_float4(0.f, 0.f, 0.f, 0.f);
    int e = 0;
    for (; e + 1 < cnt; e += 2) {
        int s0 = g_srcs[off + e];
        int s1 = g_srcs[off + e + 1];
        float4 v0 = ((const float4*)(base + (size_t)s0 * CIN))[lane];
        float4 v1 = ((const float4*)(base + (size_t)s1 * CIN))[lane];
        acc.x += v0.x + v1.x;
        acc.y += v0.y + v1.y;
        acc.z += v0.z + v1.z;
        acc.w += v0.w + v1.w;
    }
    if (e < cnt) {
        int s0 = g_srcs[off + e];
        float4 v0 = ((const float4*)(base + (size_t)s0 * CIN))[lane];
        acc.x += v0.x; acc.y += v0.y; acc.z += v0.z; acc.w += v0.w;
    }
    float s = 1.0f / (float)(cnt > 0 ? cnt : 1);
    acc.x *= s; acc.y *= s; acc.z *= s; acc.w *= s;
    ((float4*)(g_agg + (size_t)w * CIN))[lane] = acc;
}

// ---------------------------------------------------------------------------
// Fused combine GEMM with packed f32x2 FMA.
//   out = act( [x | mean_agg0 | mean_agg1] @ [Wroot ; Wrel0 ; Wrel1] + b )
// BM=128, BN=64, BK=16, 128 threads, TM=8 (4 f32x2 m-pairs) x TN=8.
// B duplicated in smem so b-pairs (b,b) load directly; a-pairs (m,m+1) come
// free from the k-major As layout.
// ---------------------------------------------------------------------------
#define FFMA2(d, a, b) \
    asm("fma.rn.f32x2 %0, %1, %2, %0;" : "+l"(d) : "l"(a), "l"(b))

template <int OUTC, bool LAYER1>
__global__ void __launch_bounds__(128)
combine_kernel(const float* __restrict__ Ax,
               const float* __restrict__ Wroot,
               const float* __restrict__ Wrel,
               const float* __restrict__ bias,
               float* __restrict__ out_param) {
    __shared__ float As[16][128];   // [k][m]
    __shared__ float Bd[16][128];   // [k][2n] duplicated

    const float* A0 = LAYER1 ? Ax : g_h;
    float*       out = LAYER1 ? g_h : out_param;

    int tid = threadIdx.x;
    int m0 = blockIdx.x * 128;
    int n0 = blockIdx.y * 64;
    int tn = (tid & 7) * 8;        // 8 output cols
    int tm = (tid >> 3) * 8;       // 8 output rows

    unsigned long long acc[4][8];
#pragma unroll
    for (int i = 0; i < 4; i++)
#pragma unroll
        for (int j = 0; j < 8; j++) acc[i][j] = 0ULL;

    int node_ld = m0 + tid;        // A loader: thread t owns row t
    int bk = tid >> 3;             // B loader coords
    int bn = (tid & 7) * 8;

    for (int kt = 0; kt < 24; kt++) {
        int seg  = kt >> 3;
        int krel = (kt & 7) * 16;
        const float* Asrc = (seg == 0) ? A0 : (g_agg + (size_t)(seg - 1) * NN * 128);
        const float* Bsrc = (seg == 0) ? Wroot : (Wrel + (size_t)(seg - 1) * 128 * OUTC);

        // A tile: thread t reads row m0+t, 16 contiguous k, stores transposed.
        {
            float4 v0 = make_float4(0.f, 0.f, 0.f, 0.f), v1 = v0, v2 = v0, v3 = v0;
            if (node_ld < NN) {
                const float4* p = (const float4*)(Asrc + (size_t)node_ld * 128 + krel);
                v0 = p[0]; v1 = p[1]; v2 = p[2]; v3 = p[3];
            }
            As[0][tid] = v0.x;  As[1][tid] = v0.y;  As[2][tid] = v0.z;  As[3][tid] = v0.w;
            As[4][tid] = v1.x;  As[5][tid] = v1.y;  As[6][tid] = v1.z;  As[7][tid] = v1.w;
            As[8][tid] = v2.x;  As[9][tid] = v2.y;  As[10][tid] = v2.z; As[11][tid] = v2.w;
            As[12][tid] = v3.x; As[13][tid] = v3.y; As[14][tid] = v3.z; As[15][tid] = v3.w;
        }
        // B tile duplicated: Bd[k][2j] = Bd[k][2j+1] = B[k][j].
        {
            const float4* p = (const float4*)(Bsrc + (size_t)(krel + bk) * OUTC + n0 + bn);
            float4 v1 = p[0], v2 = p[1];
            *(float4*)&Bd[bk][2 * bn + 0]  = make_float4(v1.x, v1.x, v1.y, v1.y);
            *(float4*)&Bd[bk][2 * bn + 4]  = make_float4(v1.z, v1.z, v1.w, v1.w);
            *(float4*)&Bd[bk][2 * bn + 8]  = make_float4(v2.x, v2.x, v2.y, v2.y);
            *(float4*)&Bd[bk][2 * bn + 12] = make_float4(v2.z, v2.z, v2.w, v2.w);
        }
        __syncthreads();

#pragma unroll
        for (int k = 0; k < 16; k++) {
            ulonglong2 a0 = *(const ulonglong2*)&As[k][tm];
            ulonglong2 a1 = *(const ulonglong2*)&As[k][tm + 4];
            ulonglong2 b0 = *(const ulonglong2*)&Bd[k][2 * tn];
            ulonglong2 b1 = *(const ulonglong2*)&Bd[k][2 * tn + 4];
            ulonglong2 b2 = *(const ulonglong2*)&Bd[k][2 * tn + 8];
            ulonglong2 b3 = *(const ulonglong2*)&Bd[k][2 * tn + 12];
            unsigned long long ap[4] = {a0.x, a0.y, a1.x, a1.y};
            unsigned long long bd[8] = {b0.x, b0.y, b1.x, b1.y, b2.x, b2.y, b3.x, b3.y};
#pragma unroll
            for (int i = 0; i < 4; i++)
#pragma unroll
                for (int j = 0; j < 8; j++) FFMA2(acc[i][j], ap[i], bd[j]);
        }
        __syncthreads();
    }

    float bv[8];
#pragma unroll
    for (int j = 0; j < 8; j++) bv[j] = bias[n0 + tn + j];

#pragma unroll
    for (int mp = 0; mp < 4; mp++) {
        float o0[8], o1[8];
#pragma unroll
        for (int j = 0; j < 8; j++) {
            float2 p;
            asm("mov.b64 {%0,%1}, %2;" : "=f"(p.x), "=f"(p.y) : "l"(acc[mp][j]));
            o0[j] = p.x + bv[j];
            o1[j] = p.y + bv[j];
            if (LAYER1) { o0[j] = fmaxf(o0[j], 0.f); o1[j] = fmaxf(o1[j], 0.f); }
        }
        int node0 = m0 + tm + 2 * mp;
        if (node0 < NN) {
            float* r = out + (size_t)node0 * OUTC + n0 + tn;
            *(float4*)(r + 0) = make_float4(o0[0], o0[1], o0[2], o0[3]);
            *(float4*)(r + 4) = make_float4(o0[4], o0[5], o0[6], o0[7]);
        }
        if (node0 + 1 < NN) {
            float* r = out + (size_t)(node0 + 1) * OUTC + n0 + tn;
            *(float4*)(r + 0) = make_float4(o1[0], o1[1], o1[2], o1[3]);
            *(float4*)(r + 4) = make_float4(o1[4], o1[5], o1[6], o1[7]);
        }
    }
}

// ---------------------------------------------------------------------------
// Row L2 normalize: one warp per node.
// ---------------------------------------------------------------------------
__global__ void normalize_kernel(float* __restrict__ out) {
    long long gtid = (long long)blockIdx.x * blockDim.x + threadIdx.x;
    int node = (int)(gtid >> 5);
    int lane = (int)(gtid & 31);
    if (node >= NN) return;
    float2* row = (float2*)(out + (size_t)node * COUT);
    float2 v = row[lane];
    float ss = v.x * v.x + v.y * v.y;
#pragma unroll
    for (int o = 16; o; o >>= 1) ss += __shfl_xor_sync(0xFFFFFFFFu, ss, o);
    float s = 1.0f / fmaxf(sqrtf(ss), 1e-12f);
    v.x *= s; v.y *= s;
    row[lane] = v;
}

// ---------------------------------------------------------------------------
extern "C" void kernel_launch(void* const* d_in, const int* in_sizes, int n_in,
                              void* d_out, int out_size) {
    const float* x       = (const float*)d_in[0];
    const void*  ei      = d_in[1];
    const void*  et      = d_in[2];
    const float* W1_rel  = (const float*)d_in[3];
    const float* W1_root = (const float*)d_in[4];
    const float* b1      = (const float*)d_in[5];
    const float* W2_rel  = (const float*)d_in[6];
    const float* W2_root = (const float*)d_in[7];
    const float* b2      = (const float*)d_in[8];
    float* out = (float*)d_out;

    const int MT = (NN + 127) / 128;   // 782

    detect_kernel<<<1, 1>>>(et);

    // CSR build (once; reused by both layers)
    zero_icnt_kernel<<<(SCAN_N + 255) / 256, 256>>>();
    count_kernel<<<(NE + 255) / 256, 256>>>(ei, et);
    scan1_kernel<<<SNB, SBS>>>();
    scan2_kernel<<<1, SBS>>>();
    scan3_kernel<<<(SCAN_N + 255) / 256, 256>>>();
    place_kernel<<<(NE + 255) / 256, 256>>>(ei, et);

    // Layer 1
    gather_kernel<<<SCAN_N * 32 / 256, 256>>>(x, 0);
    combine_kernel<CHID, true><<<dim3(MT, CHID / 64), 128>>>(x, W1_root, W1_rel, b1, nullptr);

    // Layer 2
    gather_kernel<<<SCAN_N * 32 / 256, 256>>>(x, 1);
    combine_kernel<COUT, false><<<dim3(MT, COUT / 64), 128>>>(nullptr, W2_root, W2_rel, b2, out);

    normalize_kernel<<<(NN * 32 + 255) / 256, 256>>>(out);
}

// round 3
// speedup vs baseline: 2.1056x; 2.1056x over previous
#include <cuda_runtime.h>
#include <cstdint>
#include <cstddef>

// ---------------------------------------------------------------------------
// RGCN 2-layer, mean agg, ReLU, L2 norm. N=100000, E=1600000, R=2, 128->128->64.
// Round 3: CSR gather aggregation (mean folded in) + R1's proven FFMA GEMM.
// ---------------------------------------------------------------------------

#define NN   100000
#define NE   1600000
#define NREL 2
#define CIN  128
#define CHID 128
#define COUT 64

#define SCAN_N (NREL * NN)                  // 200000 buckets
#define SBS    512
#define SNB    ((SCAN_N + SBS - 1) / SBS)   // 391

// Scratch (static device globals; no allocation allowed).
__device__ __align__(128) float g_agg[(size_t)NREL * NN * CIN];   // 102.4 MB
__device__ __align__(128) float g_h[(size_t)NN * CHID];           // 51.2 MB
__device__ int g_icnt[SCAN_N];
__device__ int g_off[SCAN_N];
__device__ int g_cur[SCAN_N];
__device__ int g_bsum[SNB];
__device__ int g_srcs[NE];
__device__ int g_is64;

// ---------------------------------------------------------------------------
// Edge dtype detection (jax x64-disabled silently downcasts int64 -> int32).
// ---------------------------------------------------------------------------
__global__ void detect_kernel(const void* et) {
    const long long* p = (const long long*)et;
    int ok = 1;
    for (int i = 0; i < 512; i++) {
        long long v = p[i];
        if (v < 0 || v >= NREL) { ok = 0; break; }
    }
    g_is64 = ok;
}

__device__ __forceinline__ long long ld_idx(const void* p, long long i, int is64) {
    if (is64) return ((const long long*)p)[i];
    return (long long)((const int*)p)[i];
}

// ---------------------------------------------------------------------------
// CSR build: count -> 2-level scan -> place.
// ---------------------------------------------------------------------------
__global__ void zero_icnt_kernel() {
    int i = blockIdx.x * blockDim.x + threadIdx.x;
    if (i < SCAN_N) g_icnt[i] = 0;
}

__global__ void count_kernel(const void* ei, const void* et) {
    int e = blockIdx.x * blockDim.x + threadIdx.x;
    if (e >= NE) return;
    int is64 = g_is64;
    int dst = (int)ld_idx(ei, (long long)NE + e, is64);
    int r   = (int)ld_idx(et, e, is64);
    atomicAdd(&g_icnt[r * NN + dst], 1);
}

__global__ void scan1_kernel() {
    __shared__ int s[SBS];
    int tid = threadIdx.x;
    int i = blockIdx.x * SBS + tid;
    int v = (i < SCAN_N) ? g_icnt[i] : 0;
    s[tid] = v;
    __syncthreads();
#pragma unroll
    for (int o = 1; o < SBS; o <<= 1) {
        int t = 0;
        if (tid >= o) t = s[tid - o];
        __syncthreads();
        if (tid >= o) s[tid] += t;
        __syncthreads();
    }
    if (i < SCAN_N) g_off[i] = s[tid] - v;          // exclusive within block
    if (tid == SBS - 1) g_bsum[blockIdx.x] = s[SBS - 1];
}

__global__ void scan2_kernel() {
    __shared__ int s[SBS];
    int tid = threadIdx.x;
    int v = (tid < SNB) ? g_bsum[tid] : 0;
    s[tid] = v;
    __syncthreads();
#pragma unroll
    for (int o = 1; o < SBS; o <<= 1) {
        int t = 0;
        if (tid >= o) t = s[tid - o];
        __syncthreads();
        if (tid >= o) s[tid] += t;
        __syncthreads();
    }
    if (tid < SNB) g_bsum[tid] = s[tid] - v;        // exclusive block offsets
}

__global__ void scan3_kernel() {
    int i = blockIdx.x * blockDim.x + threadIdx.x;
    if (i >= SCAN_N) return;
    int o = g_off[i] + g_bsum[i / SBS];
    g_off[i] = o;
    g_cur[i] = o;
}

__global__ void place_kernel(const void* ei, const void* et) {
    int e = blockIdx.x * blockDim.x + threadIdx.x;
    if (e >= NE) return;
    int is64 = g_is64;
    int src = (int)ld_idx(ei, e, is64);
    int dst = (int)ld_idx(ei, (long long)NE + e, is64);
    int r   = (int)ld_idx(et, e, is64);
    int p = atomicAdd(&g_cur[r * NN + dst], 1);
    g_srcs[p] = src;
}

// ---------------------------------------------------------------------------
// Gather-aggregate: one warp per (rel,node) bucket, lane l owns channels
// [4l,4l+4). 4-wide unroll for MLP. Mean folded into the store. Overwrites
// every row -> no zero pass needed.
// ---------------------------------------------------------------------------
__global__ void gather_kernel(const float* __restrict__ x, int use_h) {
    int gt = blockIdx.x * blockDim.x + threadIdx.x;
    int w = gt >> 5;
    int lane = gt & 31;
    if (w >= SCAN_N) return;
    const float* __restrict__ base = use_h ? g_h : x;
    int off = g_off[w];
    int cnt = g_icnt[w];
    float4 acc = make_float4(0.f, 0.f, 0.f, 0.f);
    int e = 0;
    for (; e + 4 <= cnt; e += 4) {
        int s0 = g_srcs[off + e];
        int s1 = g_srcs[off + e + 1];
        int s2 = g_srcs[off + e + 2];
        int s3 = g_srcs[off + e + 3];
        float4 v0 = ((const float4*)(base + (size_t)s0 * CIN))[lane];
        float4 v1 = ((const float4*)(base + (size_t)s1 * CIN))[lane];
        float4 v2 = ((const float4*)(base + (size_t)s2 * CIN))[lane];
        float4 v3 = ((const float4*)(base + (size_t)s3 * CIN))[lane];
        acc.x += (v0.x + v1.x) + (v2.x + v3.x);
        acc.y += (v0.y + v1.y) + (v2.y + v3.y);
        acc.z += (v0.z + v1.z) + (v2.z + v3.z);
        acc.w += (v0.w + v1.w) + (v2.w + v3.w);
    }
    for (; e < cnt; e++) {
        int s0 = g_srcs[off + e];
        float4 v0 = ((const float4*)(base + (size_t)s0 * CIN))[lane];
        acc.x += v0.x; acc.y += v0.y; acc.z += v0.z; acc.w += v0.w;
    }
    float s = 1.0f / (float)(cnt > 0 ? cnt : 1);
    acc.x *= s; acc.y *= s; acc.z *= s; acc.w *= s;
    ((float4*)(g_agg + (size_t)w * CIN))[lane] = acc;
}

// ---------------------------------------------------------------------------
// Fused combine GEMM (R1's proven version, minus the g_inv multiply):
//   out = act( [x | mean_agg0 | mean_agg1] @ [Wroot ; Wrel0 ; Wrel1] + b )
// BM=128, BN=64, BK=16, 256 threads, TM=8 TN=4.
// ---------------------------------------------------------------------------
template <int OUTC, bool LAYER1>
__global__ void combine_kernel(const float* __restrict__ Ax,
                               const float* __restrict__ Wroot,
                               const float* __restrict__ Wrel,
                               const float* __restrict__ bias,
                               float* __restrict__ out_param) {
    __shared__ float As[16][128];
    __shared__ float Bs[16][64];

    const float* A0 = LAYER1 ? Ax : g_h;
    float*       out = LAYER1 ? g_h : out_param;

    int tid = threadIdx.x;
    int m0 = blockIdx.x * 128;
    int n0 = blockIdx.y * 64;
    int tn = (tid & 15) * 4;
    int tm = (tid >> 4) * 8;

    float acc[8][4];
#pragma unroll
    for (int i = 0; i < 8; i++)
#pragma unroll
        for (int j = 0; j < 4; j++) acc[i][j] = 0.f;

    for (int kt = 0; kt < 24; kt++) {
        int seg  = kt >> 3;           // 0: root input, 1/2: relation means
        int krel = (kt & 7) * 16;     // k offset within the 128-wide segment
        const float* Asrc = (seg == 0) ? A0 : (g_agg + (size_t)(seg - 1) * NN * 128);
        const float* Bsrc = (seg == 0) ? Wroot : (Wrel + (size_t)(seg - 1) * 128 * OUTC);

        // Load A tile (128 rows x 16 k), transposed into As[k][row].
#pragma unroll
        for (int i = 0; i < 2; i++) {
            int idx = tid * 2 + i;        // 0..511
            int ar  = idx >> 2;           // row 0..127
            int ak  = (idx & 3) * 4;      // k4 offset
            int node = m0 + ar;
            float4 v = make_float4(0.f, 0.f, 0.f, 0.f);
            if (node < NN) {
                v = *(const float4*)(Asrc + (size_t)node * 128 + krel + ak);
            }
            As[ak + 0][ar] = v.x;
            As[ak + 1][ar] = v.y;
            As[ak + 2][ar] = v.z;
            As[ak + 3][ar] = v.w;
        }
        // Load B tile (16 k x 64 n).
        {
            int bk = tid >> 4;
            int bn = (tid & 15) * 4;
            float4 v = *(const float4*)(Bsrc + (size_t)(krel + bk) * OUTC + n0 + bn);
            *(float4*)&Bs[bk][bn] = v;
        }
        __syncthreads();

#pragma unroll
        for (int k = 0; k < 16; k++) {
            float4 a0 = *(const float4*)&As[k][tm];
            float4 a1 = *(const float4*)&As[k][tm + 4];
            float4 b0 = *(const float4*)&Bs[k][tn];
            float av[8] = {a0.x, a0.y, a0.z, a0.w, a1.x, a1.y, a1.z, a1.w};
            float bv[4] = {b0.x, b0.y, b0.z, b0.w};
#pragma unroll
            for (int i = 0; i < 8; i++)
#pragma unroll
                for (int j = 0; j < 4; j++) acc[i][j] += av[i] * bv[j];
        }
        __syncthreads();
    }

    float bv[4];
#pragma unroll
    for (int j = 0; j < 4; j++) bv[j] = bias[n0 + tn + j];
#pragma unroll
    for (int i = 0; i < 8; i++) {
        int node = m0 + tm + i;
        if (node < NN) {
            float4 o;
            o.x = acc[i][0] + bv[0];
            o.y = acc[i][1] + bv[1];
            o.z = acc[i][2] + bv[2];
            o.w = acc[i][3] + bv[3];
            if (LAYER1) {
                o.x = fmaxf(o.x, 0.f); o.y = fmaxf(o.y, 0.f);
                o.z = fmaxf(o.z, 0.f); o.w = fmaxf(o.w, 0.f);
            }
            *(float4*)(out + (size_t)node * OUTC + n0 + tn) = o;
        }
    }
}

// ---------------------------------------------------------------------------
// Row L2 normalize: one warp per node.
// ---------------------------------------------------------------------------
__global__ void normalize_kernel(float* __restrict__ out) {
    long long gtid = (long long)blockIdx.x * blockDim.x + threadIdx.x;
    int node = (int)(gtid >> 5);
    int lane = (int)(gtid & 31);
    if (node >= NN) return;
    float2* row = (float2*)(out + (size_t)node * COUT);
    float2 v = row[lane];
    float ss = v.x * v.x + v.y * v.y;
#pragma unroll
    for (int o = 16; o; o >>= 1) ss += __shfl_xor_sync(0xFFFFFFFFu, ss, o);
    float s = 1.0f / fmaxf(sqrtf(ss), 1e-12f);
    v.x *= s; v.y *= s;
    row[lane] = v;
}

// ---------------------------------------------------------------------------
extern "C" void kernel_launch(void* const* d_in, const int* in_sizes, int n_in,
                              void* d_out, int out_size) {
    const float* x       = (const float*)d_in[0];
    const void*  ei      = d_in[1];
    const void*  et      = d_in[2];
    const float* W1_rel  = (const float*)d_in[3];
    const float* W1_root = (const float*)d_in[4];
    const float* b1      = (const float*)d_in[5];
    const float* W2_rel  = (const float*)d_in[6];
    const float* W2_root = (const float*)d_in[7];
    const float* b2      = (const float*)d_in[8];
    float* out = (float*)d_out;

    const int MT = (NN + 127) / 128;   // 782

    detect_kernel<<<1, 1>>>(et);

    // CSR build (once; reused by both layers)
    zero_icnt_kernel<<<(SCAN_N + 255) / 256, 256>>>();
    count_kernel<<<(NE + 255) / 256, 256>>>(ei, et);
    scan1_kernel<<<SNB, SBS>>>();
    scan2_kernel<<<1, SBS>>>();
    scan3_kernel<<<(SCAN_N + 255) / 256, 256>>>();
    place_kernel<<<(NE + 255) / 256, 256>>>(ei, et);

    // Layer 1
    gather_kernel<<<SCAN_N * 32 / 256, 256>>>(x, 0);
    combine_kernel<CHID, true><<<dim3(MT, CHID / 64), 256>>>(x, W1_root, W1_rel, b1, nullptr);

    // Layer 2
    gather_kernel<<<SCAN_N * 32 / 256, 256>>>(x, 1);
    combine_kernel<COUT, false><<<dim3(MT, COUT / 64), 256>>>(nullptr, W2_root, W2_rel, b2, out);

    normalize_kernel<<<(NN * 32 + 255) / 256, 256>>>(out);
}

// round 6
// speedup vs baseline: 2.7014x; 1.2829x over previous
#include <cuda_runtime.h>
#include <cuda_bf16.h>
#include <cstdint>
#include <cstddef>

// ---------------------------------------------------------------------------
// RGCN 2-layer, mean agg, ReLU, L2 norm. N=100000, E=1600000, R=2, 128->128->64.
// Round 6: CSR gather (R3, proven) + mma.sync bf16 3-term split GEMM
// (tcgen05 is 'a'-suffix-gated and the harness targets plain sm_103).
// ---------------------------------------------------------------------------

#define NN   100000
#define NE   1600000
#define NREL 2
#define CIN  128
#define CHID 128
#define COUT 64

#define SCAN_N (NREL * NN)                  // 200000 buckets
#define SBS    512
#define SNB    ((SCAN_N + SBS - 1) / SBS)   // 391

// Scratch (static device globals; no allocation allowed).
__device__ __align__(128) float g_agg[(size_t)NREL * NN * CIN];   // 102.4 MB
__device__ __align__(128) float g_h[(size_t)NN * CHID];           // 51.2 MB
__device__ int g_icnt[SCAN_N];
__device__ int g_off[SCAN_N];
__device__ int g_cur[SCAN_N];
__device__ int g_bsum[SNB];
__device__ int g_srcs[NE];
__device__ int g_is64;

// ---------------------------------------------------------------------------
// Edge dtype detection (jax x64-disabled silently downcasts int64 -> int32).
// ---------------------------------------------------------------------------
__global__ void detect_kernel(const void* et) {
    const long long* p = (const long long*)et;
    int ok = 1;
    for (int i = 0; i < 512; i++) {
        long long v = p[i];
        if (v < 0 || v >= NREL) { ok = 0; break; }
    }
    g_is64 = ok;
}

__device__ __forceinline__ long long ld_idx(const void* p, long long i, int is64) {
    if (is64) return ((const long long*)p)[i];
    return (long long)((const int*)p)[i];
}

// ---------------------------------------------------------------------------
// CSR build: count -> 2-level scan -> place.
// ---------------------------------------------------------------------------
__global__ void zero_icnt_kernel() {
    int i = blockIdx.x * blockDim.x + threadIdx.x;
    if (i < SCAN_N) g_icnt[i] = 0;
}

__global__ void count_kernel(const void* ei, const void* et) {
    int e = blockIdx.x * blockDim.x + threadIdx.x;
    if (e >= NE) return;
    int is64 = g_is64;
    int dst = (int)ld_idx(ei, (long long)NE + e, is64);
    int r   = (int)ld_idx(et, e, is64);
    atomicAdd(&g_icnt[r * NN + dst], 1);
}

__global__ void scan1_kernel() {
    __shared__ int s[SBS];
    int tid = threadIdx.x;
    int i = blockIdx.x * SBS + tid;
    int v = (i < SCAN_N) ? g_icnt[i] : 0;
    s[tid] = v;
    __syncthreads();
#pragma unroll
    for (int o = 1; o < SBS; o <<= 1) {
        int t = 0;
        if (tid >= o) t = s[tid - o];
        __syncthreads();
        if (tid >= o) s[tid] += t;
        __syncthreads();
    }
    if (i < SCAN_N) g_off[i] = s[tid] - v;
    if (tid == SBS - 1) g_bsum[blockIdx.x] = s[SBS - 1];
}

__global__ void scan2_kernel() {
    __shared__ int s[SBS];
    int tid = threadIdx.x;
    int v = (tid < SNB) ? g_bsum[tid] : 0;
    s[tid] = v;
    __syncthreads();
#pragma unroll
    for (int o = 1; o < SBS; o <<= 1) {
        int t = 0;
        if (tid >= o) t = s[tid - o];
        __syncthreads();
        if (tid >= o) s[tid] += t;
        __syncthreads();
    }
    if (tid < SNB) g_bsum[tid] = s[tid] - v;
}

__global__ void scan3_kernel() {
    int i = blockIdx.x * blockDim.x + threadIdx.x;
    if (i >= SCAN_N) return;
    int o = g_off[i] + g_bsum[i / SBS];
    g_off[i] = o;
    g_cur[i] = o;
}

__global__ void place_kernel(const void* ei, const void* et) {
    int e = blockIdx.x * blockDim.x + threadIdx.x;
    if (e >= NE) return;
    int is64 = g_is64;
    int src = (int)ld_idx(ei, e, is64);
    int dst = (int)ld_idx(ei, (long long)NE + e, is64);
    int r   = (int)ld_idx(et, e, is64);
    int p = atomicAdd(&g_cur[r * NN + dst], 1);
    g_srcs[p] = src;
}

// ---------------------------------------------------------------------------
// Gather-aggregate: one warp per (rel,node) bucket. Mean folded in.
// ---------------------------------------------------------------------------
__global__ void gather_kernel(const float* __restrict__ x, int use_h) {
    int gt = blockIdx.x * blockDim.x + threadIdx.x;
    int w = gt >> 5;
    int lane = gt & 31;
    if (w >= SCAN_N) return;
    const float* __restrict__ base = use_h ? g_h : x;
    int off = g_off[w];
    int cnt = g_icnt[w];
    float4 acc = make_float4(0.f, 0.f, 0.f, 0.f);
    int e = 0;
    for (; e + 4 <= cnt; e += 4) {
        int s0 = g_srcs[off + e];
        int s1 = g_srcs[off + e + 1];
        int s2 = g_srcs[off + e + 2];
        int s3 = g_srcs[off + e + 3];
        float4 v0 = ((const float4*)(base + (size_t)s0 * CIN))[lane];
        float4 v1 = ((const float4*)(base + (size_t)s1 * CIN))[lane];
        float4 v2 = ((const float4*)(base + (size_t)s2 * CIN))[lane];
        float4 v3 = ((const float4*)(base + (size_t)s3 * CIN))[lane];
        acc.x += (v0.x + v1.x) + (v2.x + v3.x);
        acc.y += (v0.y + v1.y) + (v2.y + v3.y);
        acc.z += (v0.z + v1.z) + (v2.z + v3.z);
        acc.w += (v0.w + v1.w) + (v2.w + v3.w);
    }
    for (; e < cnt; e++) {
        int s0 = g_srcs[off + e];
        float4 v0 = ((const float4*)(base + (size_t)s0 * CIN))[lane];
        acc.x += v0.x; acc.y += v0.y; acc.z += v0.z; acc.w += v0.w;
    }
    float s = 1.0f / (float)(cnt > 0 ? cnt : 1);
    acc.x *= s; acc.y *= s; acc.z *= s; acc.w *= s;
    ((float4*)(g_agg + (size_t)w * CIN))[lane] = acc;
}

// ---------------------------------------------------------------------------
// bf16 split helpers. pack2(a,b) -> bf16x2 {lo=a, hi=b} (rn).
// ---------------------------------------------------------------------------
__device__ __forceinline__ uint32_t pack2(float a, float b) {
    uint32_t r;
    asm("cvt.rn.bf16x2.f32 %0, %2, %1;" : "=r"(r) : "f"(a), "f"(b));
    return r;
}
__device__ __forceinline__ float bf_lo(uint32_t p) { return __uint_as_float(p << 16); }
__device__ __forceinline__ float bf_hi(uint32_t p) { return __uint_as_float(p & 0xFFFF0000u); }

// Split two floats into hi/lo bf16x2 pairs.
__device__ __forceinline__ void split2(float x, float y, uint32_t& h, uint32_t& l) {
    h = pack2(x, y);
    l = pack2(x - bf_lo(h), y - bf_hi(h));
}

__device__ __forceinline__ void mma_bf16(float* c, uint32_t a0, uint32_t a1,
                                         uint32_t a2, uint32_t a3,
                                         uint32_t b0, uint32_t b1) {
    asm volatile(
        "mma.sync.aligned.m16n8k16.row.col.f32.bf16.bf16.f32 "
        "{%0,%1,%2,%3}, {%4,%5,%6,%7}, {%8,%9}, {%0,%1,%2,%3};"
        : "+f"(c[0]), "+f"(c[1]), "+f"(c[2]), "+f"(c[3])
        : "r"(a0), "r"(a1), "r"(a2), "r"(a3), "r"(b0), "r"(b1));
}

// ---------------------------------------------------------------------------
// Fused combine GEMM, 3-term bf16 split on tensor cores:
//   out = act( [x | agg0 | agg1] @ [Wroot;Wrel0;Wrel1] + b )
//   D = Ah*Bh + Al*Bh + Ah*Bl  (fp32 accumulate; err ~2^-18)
// 256 threads = 8 warps; warp w owns rows [16w,16w+16) x all OUTC cols.
// K=384 in 12 chunks of 32. Smem tiles padded to 20 words/row (80B) ->
// conflict-free LDS.32 fragment loads.
// ---------------------------------------------------------------------------
template <int OUTC, bool LAYER1>
__global__ void __launch_bounds__(256)
combine_mma_kernel(const float* __restrict__ Ax,
                   const float* __restrict__ Wroot,
                   const float* __restrict__ Wrel,
                   const float* __restrict__ bias,
                   float* __restrict__ out_param) {
    constexpr int NT = OUTC / 8;          // n8 tiles per warp
    __shared__ uint32_t As_hi[128][20];   // [row][k-word], 2 bf16/word, pad 4
    __shared__ uint32_t As_lo[128][20];
    __shared__ uint32_t Bs_hi[OUTC][20];  // [n][k-word]
    __shared__ uint32_t Bs_lo[OUTC][20];

    const float* A0  = LAYER1 ? Ax : g_h;
    float*       out = LAYER1 ? g_h : out_param;

    int tid  = threadIdx.x;
    int wid  = tid >> 5;
    int lane = tid & 31;
    int m0   = blockIdx.x * 128;
    int mrow = wid * 16;

    float acc[NT][4];
#pragma unroll
    for (int i = 0; i < NT; i++)
#pragma unroll
        for (int j = 0; j < 4; j++) acc[i][j] = 0.f;

    for (int c = 0; c < 12; c++) {
        int seg  = c >> 2;            // 0: root input, 1/2: relation means
        int krel = (c & 3) * 32;      // k offset within the 128-wide segment

        if (tid < 128) {
            // A loader: thread t = row t; 32 floats -> 16 hi + 16 lo words.
            const float* Asrc = (seg == 0) ? A0 : (g_agg + (size_t)(seg - 1) * NN * 128);
            int node = m0 + tid;
            bool valid = (node < NN);
            const float4* src = (const float4*)(Asrc + (size_t)node * 128 + krel);
#pragma unroll
            for (int i = 0; i < 8; i++) {
                float4 v = valid ? src[i] : make_float4(0.f, 0.f, 0.f, 0.f);
                uint32_t h0, l0, h1, l1;
                split2(v.x, v.y, h0, l0);
                split2(v.z, v.w, h1, l1);
                As_hi[tid][2 * i + 0] = h0;
                As_hi[tid][2 * i + 1] = h1;
                As_lo[tid][2 * i + 0] = l0;
                As_lo[tid][2 * i + 1] = l1;
            }
        } else if (tid - 128 < OUTC) {
            // B loader: thread owns output col n; reads W[k][n] (coalesced
            // across threads per k), transposes into [n][k] hi/lo tiles.
            const float* Bsrc = (seg == 0) ? Wroot : (Wrel + (size_t)(seg - 1) * 128 * OUTC);
            int n = tid - 128;
#pragma unroll
            for (int g = 0; g < 16; g++) {
                float v0 = Bsrc[(size_t)(krel + 2 * g + 0) * OUTC + n];
                float v1 = Bsrc[(size_t)(krel + 2 * g + 1) * OUTC + n];
                uint32_t h, l;
                split2(v0, v1, h, l);
                Bs_hi[n][g] = h;
                Bs_lo[n][g] = l;
            }
        }
        __syncthreads();

#pragma unroll
        for (int k16 = 0; k16 < 2; k16++) {
            int wk = k16 * 8 + (lane & 3);
            int r0 = mrow + (lane >> 2);
            uint32_t ah0 = As_hi[r0][wk],     ah1 = As_hi[r0 + 8][wk];
            uint32_t ah2 = As_hi[r0][wk + 4], ah3 = As_hi[r0 + 8][wk + 4];
            uint32_t al0 = As_lo[r0][wk],     al1 = As_lo[r0 + 8][wk];
            uint32_t al2 = As_lo[r0][wk + 4], al3 = As_lo[r0 + 8][wk + 4];
#pragma unroll
            for (int n8 = 0; n8 < NT; n8++) {
                int nr = n8 * 8 + (lane >> 2);
                uint32_t bh0 = Bs_hi[nr][wk], bh1 = Bs_hi[nr][wk + 4];
                mma_bf16(acc[n8], ah0, ah1, ah2, ah3, bh0, bh1);
                mma_bf16(acc[n8], al0, al1, al2, al3, bh0, bh1);
                uint32_t bl0 = Bs_lo[nr][wk], bl1 = Bs_lo[nr][wk + 4];
                mma_bf16(acc[n8], ah0, ah1, ah2, ah3, bl0, bl1);
            }
        }
        __syncthreads();
    }

    // Epilogue: c0={r, 2t}, c1={r, 2t+1}, c2/c3 at row+8.
    int r0 = m0 + mrow + (lane >> 2);
#pragma unroll
    for (int n8 = 0; n8 < NT; n8++) {
        int col = n8 * 8 + 2 * (lane & 3);
        float b0 = bias[col], b1 = bias[col + 1];
        float2 o0, o1;
        o0.x = acc[n8][0] + b0; o0.y = acc[n8][1] + b1;
        o1.x = acc[n8][2] + b0; o1.y = acc[n8][3] + b1;
        if (LAYER1) {
            o0.x = fmaxf(o0.x, 0.f); o0.y = fmaxf(o0.y, 0.f);
            o1.x = fmaxf(o1.x, 0.f); o1.y = fmaxf(o1.y, 0.f);
        }
        if (r0 < NN)     *(float2*)(out + (size_t)r0 * OUTC + col) = o0;
        if (r0 + 8 < NN) *(float2*)(out + (size_t)(r0 + 8) * OUTC + col) = o1;
    }
}

// ---------------------------------------------------------------------------
// Row L2 normalize: one warp per node.
// ---------------------------------------------------------------------------
__global__ void normalize_kernel(float* __restrict__ out) {
    long long gtid = (long long)blockIdx.x * blockDim.x + threadIdx.x;
    int node = (int)(gtid >> 5);
    int lane = (int)(gtid & 31);
    if (node >= NN) return;
    float2* row = (float2*)(out + (size_t)node * COUT);
    float2 v = row[lane];
    float ss = v.x * v.x + v.y * v.y;
#pragma unroll
    for (int o = 16; o; o >>= 1) ss += __shfl_xor_sync(0xFFFFFFFFu, ss, o);
    float s = 1.0f / fmaxf(sqrtf(ss), 1e-12f);
    v.x *= s; v.y *= s;
    row[lane] = v;
}

// ---------------------------------------------------------------------------
extern "C" void kernel_launch(void* const* d_in, const int* in_sizes, int n_in,
                              void* d_out, int out_size) {
    const float* x       = (const float*)d_in[0];
    const void*  ei      = d_in[1];
    const void*  et      = d_in[2];
    const float* W1_rel  = (const float*)d_in[3];
    const float* W1_root = (const float*)d_in[4];
    const float* b1      = (const float*)d_in[5];
    const float* W2_rel  = (const float*)d_in[6];
    const float* W2_root = (const float*)d_in[7];
    const float* b2      = (const float*)d_in[8];
    float* out = (float*)d_out;

    const int MT = (NN + 127) / 128;   // 782

    detect_kernel<<<1, 1>>>(et);

    // CSR build (once; reused by both layers)
    zero_icnt_kernel<<<(SCAN_N + 255) / 256, 256>>>();
    count_kernel<<<(NE + 255) / 256, 256>>>(ei, et);
    scan1_kernel<<<SNB, SBS>>>();
    scan2_kernel<<<1, SBS>>>();
    scan3_kernel<<<(SCAN_N + 255) / 256, 256>>>();
    place_kernel<<<(NE + 255) / 256, 256>>>(ei, et);

    // Layer 1
    gather_kernel<<<SCAN_N * 32 / 256, 256>>>(x, 0);
    combine_mma_kernel<CHID, true><<<MT, 256>>>(x, W1_root, W1_rel, b1, nullptr);

    // Layer 2
    gather_kernel<<<SCAN_N * 32 / 256, 256>>>(x, 1);
    combine_mma_kernel<COUT, false><<<MT, 256>>>(nullptr, W2_root, W2_rel, b2, out);

    normalize_kernel<<<(NN * 32 + 255) / 256, 256>>>(out);
}